// round 1
// baseline (speedup 1.0000x reference)
#include <cuda_runtime.h>

// Problem: x [8, 65536, 256] fp32. Per-sample classical Gram-Schmidt over the
// 8 model vectors (dim 256). Output [8, 65536, 256].
//
// Layout: x[(model*65536 + sample)*256 + dim].
//
// Strategy: one warp per sample. Lane l owns dims [4l,4l+4) and [128+4l,128+4l+4)
// of every vector (two float4 loads per vector, fully coalesced). All 8 vectors
// stay in registers (64 floats/lane). Dot products via warp shuffle reductions.
// Purely HBM-bound: 1 GB total traffic -> ~150us floor on GB300.

#define NSAMP 65536
#define NDIM  256
#define NMOD  8

__device__ __forceinline__ float warp_sum(float v) {
#pragma unroll
    for (int o = 16; o; o >>= 1)
        v += __shfl_xor_sync(0xffffffffu, v, o);
    return v;
}

__device__ __forceinline__ float dot8(const float4& p0, const float4& p1,
                                      const float4& q0, const float4& q1) {
    return p0.x * q0.x + p0.y * q0.y + p0.z * q0.z + p0.w * q0.w
         + p1.x * q1.x + p1.y * q1.y + p1.z * q1.z + p1.w * q1.w;
}

__global__ __launch_bounds__(256)
void gram_schmidt_kernel(const float* __restrict__ x, float* __restrict__ out) {
    const int warp = (blockIdx.x * blockDim.x + threadIdx.x) >> 5;
    const int lane = threadIdx.x & 31;
    if (warp >= NSAMP) return;

    const size_t samp_off     = (size_t)warp * NDIM;
    const size_t model_stride = (size_t)NSAMP * NDIM;
    const int d0 = 4 * lane;        // dims [d0, d0+4)
    const int d1 = 128 + 4 * lane;  // dims [d1, d1+4)

    // Load all 8 vectors up front (16 independent LDG.128 -> deep MLP).
    float4 a[NMOD][2];
#pragma unroll
    for (int i = 0; i < NMOD; i++) {
        const float* p = x + (size_t)i * model_stride + samp_off;
        a[i][0] = *reinterpret_cast<const float4*>(p + d0);
        a[i][1] = *reinterpret_cast<const float4*>(p + d1);
    }

#pragma unroll
    for (int i = 0; i < NMOD; i++) {
        // Classical GS: all projection coefficients computed against the
        // ORIGINAL v (= a[i] before any subtraction), matching the reference.
        float c[NMOD];
#pragma unroll
        for (int k = 0; k < NMOD; k++) {
            if (k < i) {
                float p = dot8(a[i][0], a[i][1], a[k][0], a[k][1]);
                c[k] = warp_sum(p);
            }
        }
#pragma unroll
        for (int k = 0; k < NMOD; k++) {
            if (k < i) {
                a[i][0].x -= c[k] * a[k][0].x;
                a[i][0].y -= c[k] * a[k][0].y;
                a[i][0].z -= c[k] * a[k][0].z;
                a[i][0].w -= c[k] * a[k][0].w;
                a[i][1].x -= c[k] * a[k][1].x;
                a[i][1].y -= c[k] * a[k][1].y;
                a[i][1].z -= c[k] * a[k][1].z;
                a[i][1].w -= c[k] * a[k][1].w;
            }
        }
        // Normalize.
        float nrm2 = warp_sum(dot8(a[i][0], a[i][1], a[i][0], a[i][1]));
        float inv = rsqrtf(nrm2);
        a[i][0].x *= inv; a[i][0].y *= inv; a[i][0].z *= inv; a[i][0].w *= inv;
        a[i][1].x *= inv; a[i][1].y *= inv; a[i][1].z *= inv; a[i][1].w *= inv;

        // Store this basis vector (coalesced STG.128).
        float* q = out + (size_t)i * model_stride + samp_off;
        *reinterpret_cast<float4*>(q + d0) = a[i][0];
        *reinterpret_cast<float4*>(q + d1) = a[i][1];
    }
}

extern "C" void kernel_launch(void* const* d_in, const int* in_sizes, int n_in,
                              void* d_out, int out_size) {
    const float* x = (const float*)d_in[0];
    float* out = (float*)d_out;
    // 65536 samples, 1 warp each, 8 warps (256 threads) per block -> 8192 blocks.
    gram_schmidt_kernel<<<NSAMP / 8, 256>>>(x, out);
}

// round 3
// speedup vs baseline: 1.0141x; 1.0141x over previous
#include <cuda_runtime.h>

// Problem: x [8, 65536, 256] fp32. Per-sample classical Gram-Schmidt over the
// 8 model vectors (dim 256). Output [8, 65536, 256].
//
// One warp per sample; lane l owns dims [4l,4l+4) and [128+4l,128+4l+4) of all
// 8 vectors (64 floats/lane in registers). Warp-shuffle dot products.
// HBM-bound: 1 GB total traffic. R2 changes vs R1:
//   - __ldcs / __stcs streaming hints (zero-reuse stream, keep L2 clean)
//   - all 16 STG.128 deferred to one tail burst (R-phase / W-phase separation)

#define NSAMP 65536
#define NDIM  256
#define NMOD  8

__device__ __forceinline__ float warp_sum(float v) {
#pragma unroll
    for (int o = 16; o; o >>= 1)
        v += __shfl_xor_sync(0xffffffffu, v, o);
    return v;
}

__device__ __forceinline__ float dot8(const float4& p0, const float4& p1,
                                      const float4& q0, const float4& q1) {
    return p0.x * q0.x + p0.y * q0.y + p0.z * q0.z + p0.w * q0.w
         + p1.x * q1.x + p1.y * q1.y + p1.z * q1.z + p1.w * q1.w;
}

__global__ __launch_bounds__(256)
void gram_schmidt_kernel(const float* __restrict__ x, float* __restrict__ out) {
    const int warp = (blockIdx.x * blockDim.x + threadIdx.x) >> 5;
    const int lane = threadIdx.x & 31;
    if (warp >= NSAMP) return;

    const size_t samp_off     = (size_t)warp * NDIM;
    const size_t model_stride = (size_t)NSAMP * NDIM;
    const int d0 = 4 * lane;        // dims [d0, d0+4)
    const int d1 = 128 + 4 * lane;  // dims [d1, d1+4)

    // Load all 8 vectors up front (16 independent LDG.128.CS -> deep MLP).
    float4 a[NMOD][2];
#pragma unroll
    for (int i = 0; i < NMOD; i++) {
        const float* p = x + (size_t)i * model_stride + samp_off;
        a[i][0] = __ldcs(reinterpret_cast<const float4*>(p + d0));
        a[i][1] = __ldcs(reinterpret_cast<const float4*>(p + d1));
    }

#pragma unroll
    for (int i = 0; i < NMOD; i++) {
        // Classical GS: all projection coefficients computed against the
        // ORIGINAL v (= a[i] before any subtraction), matching the reference.
        float c[NMOD];
#pragma unroll
        for (int k = 0; k < NMOD; k++) {
            if (k < i) {
                float p = dot8(a[i][0], a[i][1], a[k][0], a[k][1]);
                c[k] = warp_sum(p);
            }
        }
#pragma unroll
        for (int k = 0; k < NMOD; k++) {
            if (k < i) {
                a[i][0].x -= c[k] * a[k][0].x;
                a[i][0].y -= c[k] * a[k][0].y;
                a[i][0].z -= c[k] * a[k][0].z;
                a[i][0].w -= c[k] * a[k][0].w;
                a[i][1].x -= c[k] * a[k][1].x;
                a[i][1].y -= c[k] * a[k][1].y;
                a[i][1].z -= c[k] * a[k][1].z;
                a[i][1].w -= c[k] * a[k][1].w;
            }
        }
        // Normalize.
        float nrm2 = warp_sum(dot8(a[i][0], a[i][1], a[i][0], a[i][1]));
        float inv = rsqrtf(nrm2);
        a[i][0].x *= inv; a[i][0].y *= inv; a[i][0].z *= inv; a[i][0].w *= inv;
        a[i][1].x *= inv; a[i][1].y *= inv; a[i][1].z *= inv; a[i][1].w *= inv;
    }

    // Tail store burst: 16 contiguous STG.128.CS, separated from the load phase.
#pragma unroll
    for (int i = 0; i < NMOD; i++) {
        float* q = out + (size_t)i * model_stride + samp_off;
        __stcs(reinterpret_cast<float4*>(q + d0), a[i][0]);
        __stcs(reinterpret_cast<float4*>(q + d1), a[i][1]);
    }
}

extern "C" void kernel_launch(void* const* d_in, const int* in_sizes, int n_in,
                              void* d_out, int out_size) {
    const float* x = (const float*)d_in[0];
    float* out = (float*)d_out;
    // 65536 samples, 1 warp each, 8 warps (256 threads) per block -> 8192 blocks.
    gram_schmidt_kernel<<<NSAMP / 8, 256>>>(x, out);
}